// round 11
// baseline (speedup 1.0000x reference)
#include <cuda_runtime.h>
#include <cuda_fp16.h>
#include <math.h>
#include <stdint.h>

#define NN 50000
#define HH 256
#define NE 300000
#define H3 (3*HH)
#define KP 256
#define NPAD (NN + 128)

// ---------------- scratch ----------------------------------------------------
__device__ float g_h0[NN*HH];
__device__ float g_h1[NN*HH];
__device__ float g_agg[NN*HH];
__device__ __half g_m16[(size_t)NN*HH];
__device__ __half g_h16a[(size_t)NPAD*HH];
__device__ __half g_h16b[(size_t)NPAD*HH];

// fp16 weights, [rows, 256] K-major
__device__ __half g_wred[HH*KP];
__device__ __half g_wggc[8*HH*KP];
__device__ __half g_wih[H3*KP];
__device__ __half g_whh[H3*KP];

// ---------------- weight conversion ------------------------------------------
__global__ void conv_w(const float* __restrict__ W, __half* __restrict__ o,
                       int Nrows, int Ksrc)
{
    int t = blockIdx.x * blockDim.x + threadIdx.x;
    if (t >= Nrows * KP) return;
    int n = t >> 8, k = t & 255;
    float v = (k < Ksrc) ? W[(size_t)n * Ksrc + k] : 0.f;
    o[t] = __float2half_rn(v);
}

__global__ void conv_wggcT(const float* __restrict__ W, __half* __restrict__ o)
{
    int t = blockIdx.x * blockDim.x + threadIdx.x;
    if (t >= 8 * HH * KP) return;
    int s = t >> 16, n = (t >> 8) & 255, k = t & 255;
    o[t] = __float2half_rn(W[((size_t)s << 16) + (size_t)k * HH + n]);
}

// ---------------- asm helpers ------------------------------------------------
__device__ __forceinline__ uint32_t smem_u32(const void* p) {
    uint32_t a;
    asm("{ .reg .u64 t; cvta.to.shared.u64 t, %1; cvt.u32.u64 %0, t; }" : "=r"(a) : "l"(p));
    return a;
}
__device__ __forceinline__ void ldmx4(uint32_t* r, uint32_t addr) {
    asm volatile("ldmatrix.sync.aligned.m8n8.x4.shared.b16 {%0,%1,%2,%3}, [%4];"
                 : "=r"(r[0]), "=r"(r[1]), "=r"(r[2]), "=r"(r[3]) : "r"(addr));
}
__device__ __forceinline__ void mma16816(float* d, const uint32_t* a, uint32_t b0, uint32_t b1) {
    asm volatile(
        "mma.sync.aligned.m16n8k16.row.col.f32.f16.f16.f32 "
        "{%0,%1,%2,%3}, {%4,%5,%6,%7}, {%8,%9}, {%0,%1,%2,%3};"
        : "+f"(d[0]), "+f"(d[1]), "+f"(d[2]), "+f"(d[3])
        : "r"(a[0]), "r"(a[1]), "r"(a[2]), "r"(a[3]), "r"(b0), "r"(b1));
}
__device__ __forceinline__ void cpa16(uint32_t dst, const void* src) {
    asm volatile("cp.async.ca.shared.global [%0], [%1], 16;" :: "r"(dst), "l"(src) : "memory");
}
__device__ __forceinline__ void cpa_commit() {
    asm volatile("cp.async.commit_group;" ::: "memory");
}
__device__ __forceinline__ void cpa_wait0() {
    asm volatile("cp.async.wait_group 0;" ::: "memory");
}

#define LDSW 40

// ============ GEMM A=fp32 (reduce): C = A @ B^T + bias, writes f32 + f16 ====
#define ARR (128*LDSW)
#define STG (2*ARR)
#define SMEM_G (2*STG*2)

__global__ __launch_bounds__(256)
void mma_gemm(const float* __restrict__ A, const __half* __restrict__ B,
              const float* __restrict__ bias, float* __restrict__ C,
              __half* __restrict__ C16, int M, int N, int Ksrc)
{
    extern __shared__ __half smp[];
    const int tid = threadIdx.x, lane = tid & 31, wid = tid >> 5;
    const int bm = blockIdx.y * 128, bn = blockIdx.x * 128;
    const int wm = (wid & 3) * 32, wn = (wid >> 2) * 64;

    float c[2][8][4];
    #pragma unroll
    for (int i = 0; i < 2; i++)
        #pragma unroll
        for (int j = 0; j < 8; j++)
            #pragma unroll
            for (int q = 0; q < 4; q++) c[i][j][q] = 0.f;

    const int lrow = tid >> 1, lcol = (tid & 1) * 16;
    const bool rv = (bm + lrow) < M;
    const float* Arow = A + (size_t)(bm + lrow) * Ksrc + lcol;
    const __half* Brow = B + (size_t)(bn + lrow) * KP + lcol;

    const uint32_t u0 = smem_u32(smp);
    const int lodst = lrow * LDSW + lcol;
    const uint32_t bdst = u0 + (uint32_t)(ARR + lodst) * 2;

    const int aro = (lane & 7) + ((lane >> 3) & 1) * 8;
    const int ako = ((lane >> 4) & 1) * 8;
    const int bro = (lane & 7) + ((lane >> 4) & 1) * 8;
    const int bko = ((lane >> 3) & 1) * 8;

    {
        #pragma unroll
        for (int q = 0; q < 4; q++) {
            int k = lcol + q * 4;
            float4 v = make_float4(0.f,0.f,0.f,0.f);
            if (rv && k < Ksrc) v = *(const float4*)(Arow + q * 4);
            __half2 p0 = __floats2half2_rn(v.x, v.y);
            __half2 p1 = __floats2half2_rn(v.z, v.w);
            int o = lodst + q * 4;
            *(__half2*)&smp[o] = p0; *(__half2*)&smp[o+2] = p1;
        }
        cpa16(bdst, Brow); cpa16(bdst + 16, Brow + 8);
        cpa_commit();
    }

    for (int ch = 0; ch < 8; ch++) {
        const int cur = ch & 1, nxt = cur ^ 1;
        cpa_wait0();
        __syncthreads();
        float ar[16];
        if (ch < 7) {
            const int kn = (ch + 1) * 32;
            #pragma unroll
            for (int q = 0; q < 4; q++) {
                int k = kn + lcol + q * 4;
                float4 v = make_float4(0.f,0.f,0.f,0.f);
                if (rv && k < Ksrc) v = *(const float4*)(Arow + kn + q * 4);
                ar[q*4+0]=v.x; ar[q*4+1]=v.y; ar[q*4+2]=v.z; ar[q*4+3]=v.w;
            }
            const uint32_t sb = (uint32_t)(nxt * STG) * 2;
            cpa16(bdst + sb, Brow + kn); cpa16(bdst + sb + 16, Brow + kn + 8);
            cpa_commit();
        }
        const uint32_t base = u0 + (uint32_t)(cur * STG) * 2;
        const uint32_t uA = base, uB = base + ARR * 2;
        #pragma unroll
        for (int kh = 0; kh < 2; kh++) {
            const int kb = kh * 16;
            uint32_t ah[2][4];
            #pragma unroll
            for (int mt = 0; mt < 2; mt++)
                ldmx4(ah[mt], uA + (uint32_t)(((wm + mt*16 + aro) * LDSW + kb + ako) * 2));
            #pragma unroll
            for (int ng = 0; ng < 4; ng++) {
                uint32_t bh[4];
                ldmx4(bh, uB + (uint32_t)(((wn + ng*16 + bro) * LDSW + kb + bko) * 2));
                #pragma unroll
                for (int mt = 0; mt < 2; mt++) {
                    mma16816(c[mt][2*ng],   ah[mt], bh[0], bh[1]);
                    mma16816(c[mt][2*ng+1], ah[mt], bh[2], bh[3]);
                }
            }
        }
        if (ch < 7) {
            __half* sA = smp + nxt * STG;
            #pragma unroll
            for (int q = 0; q < 4; q++) {
                __half2 p0 = __floats2half2_rn(ar[q*4+0], ar[q*4+1]);
                __half2 p1 = __floats2half2_rn(ar[q*4+2], ar[q*4+3]);
                int o = lodst + q * 4;
                *(__half2*)&sA[o] = p0; *(__half2*)&sA[o+2] = p1;
            }
        }
    }

    #pragma unroll
    for (int mt = 0; mt < 2; mt++) {
        int row = bm + wm + mt * 16 + (lane >> 2);
        #pragma unroll
        for (int nidx = 0; nidx < 8; nidx++) {
            int col = bn + wn + nidx * 8 + (lane & 3) * 2;
            float b0 = 0.f, b1 = 0.f;
            if (bias) { b0 = bias[col]; b1 = bias[col + 1]; }
            float v00 = c[mt][nidx][0] + b0, v01 = c[mt][nidx][1] + b1;
            float v10 = c[mt][nidx][2] + b0, v11 = c[mt][nidx][3] + b1;
            if (row < M) {
                *(float2*)(C + (size_t)row * N + col) = make_float2(v00, v01);
                *(__half2*)(C16 + (size_t)row * N + col) = __floats2half2_rn(v00, v01);
            }
            if (row + 8 < M) {
                *(float2*)(C + (size_t)(row + 8) * N + col) = make_float2(v10, v11);
                *(__half2*)(C16 + (size_t)(row + 8) * N + col) = __floats2half2_rn(v10, v11);
            }
        }
    }
}

// ============ GEMM A=fp16 (ggc): m16 = A @ B^T (fp16 out), zeroes agg =======
__global__ __launch_bounds__(256)
void mma_gemm16(const __half* __restrict__ A, const __half* __restrict__ B,
                __half* __restrict__ C16, float4* __restrict__ aggz,
                int M, int N)
{
    extern __shared__ __half smp[];
    const int tid = threadIdx.x, lane = tid & 31, wid = tid >> 5;
    const int bm = blockIdx.y * 128, bn = blockIdx.x * 128;
    const int wm = (wid & 3) * 32, wn = (wid >> 2) * 64;

    float c[2][8][4];
    #pragma unroll
    for (int i = 0; i < 2; i++)
        #pragma unroll
        for (int j = 0; j < 8; j++)
            #pragma unroll
            for (int q = 0; q < 4; q++) c[i][j][q] = 0.f;

    const int lrow = tid >> 1, lcol = (tid & 1) * 16;
    const __half* Arow = A + (size_t)(bm + lrow) * KP + lcol;
    const __half* Brow = B + (size_t)(bn + lrow) * KP + lcol;

    const uint32_t u0 = smem_u32(smp);
    const int lodst = lrow * LDSW + lcol;
    const uint32_t adst = u0 + (uint32_t)lodst * 2;
    const uint32_t bdst = u0 + (uint32_t)(ARR + lodst) * 2;

    const int aro = (lane & 7) + ((lane >> 3) & 1) * 8;
    const int ako = ((lane >> 4) & 1) * 8;
    const int bro = (lane & 7) + ((lane >> 4) & 1) * 8;
    const int bko = ((lane >> 3) & 1) * 8;

    cpa16(adst, Arow); cpa16(adst + 16, Arow + 8);
    cpa16(bdst, Brow); cpa16(bdst + 16, Brow + 8);
    cpa_commit();

    // ---- zero a slice of agg (runs right before scatter in-stream) ----
    {
        const int nblk = gridDim.x * gridDim.y;
        const int slice = blockIdx.y * gridDim.x + blockIdx.x;
        const int total4 = NN * HH / 4;
        const int per = (total4 + nblk - 1) / nblk;
        int s0 = slice * per;
        int s1 = min(s0 + per, total4);
        const float4 z = make_float4(0.f,0.f,0.f,0.f);
        for (int i = s0 + tid; i < s1; i += 256) aggz[i] = z;
    }

    for (int ch = 0; ch < 8; ch++) {
        const int cur = ch & 1, nxt = cur ^ 1;
        cpa_wait0();
        __syncthreads();
        if (ch < 7) {
            const int kn = (ch + 1) * 32;
            const uint32_t sb = (uint32_t)(nxt * STG) * 2;
            cpa16(adst + sb, Arow + kn); cpa16(adst + sb + 16, Arow + kn + 8);
            cpa16(bdst + sb, Brow + kn); cpa16(bdst + sb + 16, Brow + kn + 8);
            cpa_commit();
        }
        const uint32_t base = u0 + (uint32_t)(cur * STG) * 2;
        const uint32_t uA = base, uB = base + ARR * 2;
        #pragma unroll
        for (int kh = 0; kh < 2; kh++) {
            const int kb = kh * 16;
            uint32_t ah[2][4];
            #pragma unroll
            for (int mt = 0; mt < 2; mt++)
                ldmx4(ah[mt], uA + (uint32_t)(((wm + mt*16 + aro) * LDSW + kb + ako) * 2));
            #pragma unroll
            for (int ng = 0; ng < 4; ng++) {
                uint32_t bh[4];
                ldmx4(bh, uB + (uint32_t)(((wn + ng*16 + bro) * LDSW + kb + bko) * 2));
                #pragma unroll
                for (int mt = 0; mt < 2; mt++) {
                    mma16816(c[mt][2*ng],   ah[mt], bh[0], bh[1]);
                    mma16816(c[mt][2*ng+1], ah[mt], bh[2], bh[3]);
                }
            }
        }
    }

    #pragma unroll
    for (int mt = 0; mt < 2; mt++) {
        int row = bm + wm + mt * 16 + (lane >> 2);
        #pragma unroll
        for (int nidx = 0; nidx < 8; nidx++) {
            int col = bn + wn + nidx * 8 + (lane & 3) * 2;
            if (row < M)
                *(__half2*)(C16 + (size_t)row * N + col) =
                    __floats2half2_rn(c[mt][nidx][0], c[mt][nidx][1]);
            if (row + 8 < M)
                *(__half2*)(C16 + (size_t)(row + 8) * N + col) =
                    __floats2half2_rn(c[mt][nidx][2], c[mt][nidx][3]);
        }
    }
}

// ============ fused gi+gh GEMM + GRU (K-chunk 64, 4 chunks, 184KB smem) =====
#define LDS64 72
#define ARRA6 (128*LDS64)     // 9216 halves
#define ARRW6 (64*LDS64)      // 4608 halves
#define STGF (2*ARRA6 + 6*ARRW6)   // 46080 halves
#define SMEM_F (2*STGF*2)          // 184320 bytes

__global__ __launch_bounds__(256)
void gru_fused(const float* __restrict__ agg32, const __half* __restrict__ h16,
               const float* __restrict__ h32,
               const __half* __restrict__ Wih, const __half* __restrict__ Whh,
               const float* __restrict__ b_ih, const float* __restrict__ b_hh,
               float* __restrict__ h32n, __half* __restrict__ h16n, int M)
{
    extern __shared__ __half smp[];
    const int tid = threadIdx.x, lane = tid & 31, wid = tid >> 5;
    const int bm = blockIdx.y * 128, bn = blockIdx.x * 64;
    const int wm = (wid & 3) * 32, wn = (wid >> 2) * 32;

    float cr[2][4][4], cz[2][4][4], cin[2][4][4], chn[2][4][4];
    #pragma unroll
    for (int mt = 0; mt < 2; mt++)
        #pragma unroll
        for (int f = 0; f < 4; f++)
            #pragma unroll
            for (int q = 0; q < 4; q++)
            { cr[mt][f][q]=0.f; cz[mt][f][q]=0.f; cin[mt][f][q]=0.f; chn[mt][f][q]=0.f; }

    // A loader: row = tid>>1 (0..127), 32-col seg at (tid&1)*32
    const int arow = tid >> 1, aseg = (tid & 1) * 32;
    const bool rv = (bm + arow) < M;
    const float* pAg = agg32 + (size_t)(bm + arow) * HH + aseg;
    const __half* pAh = h16   + (size_t)(bm + arow) * KP + aseg;
    // W loader: row = tid>>2 (0..63), 16-col seg at (tid&3)*16
    const int wrow = tid >> 2, wseg = (tid & 3) * 16;
    const __half* pW[6];
    pW[0] = Wih + (size_t)(bn + wrow) * KP + wseg;
    pW[1] = Whh + (size_t)(bn + wrow) * KP + wseg;
    pW[2] = Wih + (size_t)(256 + bn + wrow) * KP + wseg;
    pW[3] = Whh + (size_t)(256 + bn + wrow) * KP + wseg;
    pW[4] = Wih + (size_t)(512 + bn + wrow) * KP + wseg;
    pW[5] = Whh + (size_t)(512 + bn + wrow) * KP + wseg;

    const uint32_t u0 = smem_u32(smp);
    const int aodst = arow * LDS64 + aseg;
    const uint32_t ahdst = u0 + (uint32_t)(ARRA6 + aodst) * 2;
    const uint32_t wdst0 = u0 + (uint32_t)(2*ARRA6 + wrow * LDS64 + wseg) * 2;

    const int aro = (lane & 7) + ((lane >> 3) & 1) * 8;
    const int ako = ((lane >> 4) & 1) * 8;
    const int bro = (lane & 7) + ((lane >> 4) & 1) * 8;
    const int bko = ((lane >> 3) & 1) * 8;

    // prologue: chunk 0 (64 wide)
    {
        #pragma unroll
        for (int q = 0; q < 8; q++) {
            float4 v = rv ? *(const float4*)(pAg + q * 4) : make_float4(0.f,0.f,0.f,0.f);
            __half2 p0 = __floats2half2_rn(v.x, v.y);
            __half2 p1 = __floats2half2_rn(v.z, v.w);
            int o = aodst + q * 4;
            *(__half2*)&smp[o] = p0; *(__half2*)&smp[o+2] = p1;
        }
        #pragma unroll
        for (int j = 0; j < 4; j++) cpa16(ahdst + j * 16, pAh + j * 8);
        #pragma unroll
        for (int s = 0; s < 6; s++) {
            cpa16(wdst0 + (uint32_t)(s * ARRW6) * 2,      pW[s]);
            cpa16(wdst0 + (uint32_t)(s * ARRW6) * 2 + 16, pW[s] + 8);
        }
        cpa_commit();
    }

    for (int ch = 0; ch < 4; ch++) {
        const int cur = ch & 1, nxt = cur ^ 1;
        cpa_wait0();
        __syncthreads();
        float ar[32];
        if (ch < 3) {
            const int kn = (ch + 1) * 64;
            #pragma unroll
            for (int q = 0; q < 8; q++) {
                float4 v = rv ? *(const float4*)(pAg + kn + q * 4) : make_float4(0.f,0.f,0.f,0.f);
                ar[q*4+0]=v.x; ar[q*4+1]=v.y; ar[q*4+2]=v.z; ar[q*4+3]=v.w;
            }
            const uint32_t sb = (uint32_t)(nxt * STGF) * 2;
            #pragma unroll
            for (int j = 0; j < 4; j++) cpa16(ahdst + sb + j * 16, pAh + kn + j * 8);
            #pragma unroll
            for (int s = 0; s < 6; s++) {
                cpa16(wdst0 + sb + (uint32_t)(s * ARRW6) * 2,      pW[s] + kn);
                cpa16(wdst0 + sb + (uint32_t)(s * ARRW6) * 2 + 16, pW[s] + kn + 8);
            }
            cpa_commit();
        }

        const uint32_t base = u0 + (uint32_t)(cur * STGF) * 2;
        const uint32_t uAg = base, uAh = base + (uint32_t)ARRA6 * 2;
        #pragma unroll
        for (int kh = 0; kh < 4; kh++) {
            const int kb = kh * 16;
            uint32_t ag[2][4], ah[2][4];
            #pragma unroll
            for (int mt = 0; mt < 2; mt++) {
                const uint32_t ao = (uint32_t)(((wm + mt*16 + aro) * LDS64 + kb + ako) * 2);
                ldmx4(ag[mt], uAg + ao);
                ldmx4(ah[mt], uAh + ao);
            }
            #pragma unroll
            for (int ng = 0; ng < 2; ng++) {
                const uint32_t bo = (uint32_t)(((wn + ng*16 + bro) * LDS64 + kb + bko) * 2);
                uint32_t bb[4];
                ldmx4(bb, base + (uint32_t)(2*ARRA6 + 0*ARRW6) * 2 + bo);
                #pragma unroll
                for (int mt = 0; mt < 2; mt++) {
                    mma16816(cr[mt][2*ng],   ag[mt], bb[0], bb[1]);
                    mma16816(cr[mt][2*ng+1], ag[mt], bb[2], bb[3]);
                }
                ldmx4(bb, base + (uint32_t)(2*ARRA6 + 1*ARRW6) * 2 + bo);
                #pragma unroll
                for (int mt = 0; mt < 2; mt++) {
                    mma16816(cr[mt][2*ng],   ah[mt], bb[0], bb[1]);
                    mma16816(cr[mt][2*ng+1], ah[mt], bb[2], bb[3]);
                }
                ldmx4(bb, base + (uint32_t)(2*ARRA6 + 2*ARRW6) * 2 + bo);
                #pragma unroll
                for (int mt = 0; mt < 2; mt++) {
                    mma16816(cz[mt][2*ng],   ag[mt], bb[0], bb[1]);
                    mma16816(cz[mt][2*ng+1], ag[mt], bb[2], bb[3]);
                }
                ldmx4(bb, base + (uint32_t)(2*ARRA6 + 3*ARRW6) * 2 + bo);
                #pragma unroll
                for (int mt = 0; mt < 2; mt++) {
                    mma16816(cz[mt][2*ng],   ah[mt], bb[0], bb[1]);
                    mma16816(cz[mt][2*ng+1], ah[mt], bb[2], bb[3]);
                }
                ldmx4(bb, base + (uint32_t)(2*ARRA6 + 4*ARRW6) * 2 + bo);
                #pragma unroll
                for (int mt = 0; mt < 2; mt++) {
                    mma16816(cin[mt][2*ng],   ag[mt], bb[0], bb[1]);
                    mma16816(cin[mt][2*ng+1], ag[mt], bb[2], bb[3]);
                }
                ldmx4(bb, base + (uint32_t)(2*ARRA6 + 5*ARRW6) * 2 + bo);
                #pragma unroll
                for (int mt = 0; mt < 2; mt++) {
                    mma16816(chn[mt][2*ng],   ah[mt], bb[0], bb[1]);
                    mma16816(chn[mt][2*ng+1], ah[mt], bb[2], bb[3]);
                }
            }
        }

        if (ch < 3) {
            __half* sA = smp + nxt * STGF;
            #pragma unroll
            for (int q = 0; q < 8; q++) {
                __half2 p0 = __floats2half2_rn(ar[q*4+0], ar[q*4+1]);
                __half2 p1 = __floats2half2_rn(ar[q*4+2], ar[q*4+3]);
                int o = aodst + q * 4;
                *(__half2*)&sA[o] = p0; *(__half2*)&sA[o+2] = p1;
            }
        }
    }

    // ---- GRU epilogue ----
    #pragma unroll
    for (int mt = 0; mt < 2; mt++) {
        const int r0 = bm + wm + mt * 16 + (lane >> 2);
        #pragma unroll
        for (int f = 0; f < 4; f++) {
            const int col = bn + wn + f * 8 + (lane & 3) * 2;
            const float br0 = __ldg(b_ih + col)       + __ldg(b_hh + col);
            const float br1 = __ldg(b_ih + col + 1)   + __ldg(b_hh + col + 1);
            const float bz0 = __ldg(b_ih + 256 + col) + __ldg(b_hh + 256 + col);
            const float bz1 = __ldg(b_ih + 257 + col) + __ldg(b_hh + 257 + col);
            const float bin0 = __ldg(b_ih + 512 + col),   bin1 = __ldg(b_ih + 513 + col);
            const float bhn0 = __ldg(b_hh + 512 + col),   bhn1 = __ldg(b_hh + 513 + col);
            #pragma unroll
            for (int e = 0; e < 2; e++) {
                const int row = r0 + e * 8;
                if (row >= M) continue;
                float2 hv = *(const float2*)(h32 + (size_t)row * HH + col);
                float rr0 = 1.f / (1.f + __expf(-(cr[mt][f][2*e]   + br0)));
                float rr1 = 1.f / (1.f + __expf(-(cr[mt][f][2*e+1] + br1)));
                float zz0 = 1.f / (1.f + __expf(-(cz[mt][f][2*e]   + bz0)));
                float zz1 = 1.f / (1.f + __expf(-(cz[mt][f][2*e+1] + bz1)));
                float nn0 = tanhf(cin[mt][f][2*e]   + bin0 + rr0 * (chn[mt][f][2*e]   + bhn0));
                float nn1 = tanhf(cin[mt][f][2*e+1] + bin1 + rr1 * (chn[mt][f][2*e+1] + bhn1));
                float o0 = (1.f - zz0) * nn0 + zz0 * hv.x;
                float o1 = (1.f - zz1) * nn1 + zz1 * hv.y;
                *(float2*)(h32n + (size_t)row * HH + col) = make_float2(o0, o1);
                *(__half2*)(h16n + (size_t)row * HH + col) = __floats2half2_rn(o0, o1);
            }
        }
    }
}

// ---------------- scatter: agg[dst] += m16[src] (32 threads/edge) -----------
__global__ void scatter_kernel(const __half* __restrict__ m16,
                               const int* __restrict__ src,
                               const int* __restrict__ dst,
                               float* __restrict__ agg)
{
    long long t = (long long)blockIdx.x * blockDim.x + threadIdx.x;
    int e = (int)(t >> 5);
    if (e >= NE) return;
    int c = ((int)t & 31) << 3;
    int s = __ldg(src + e);
    int d = __ldg(dst + e);
    uint4 raw = *(const uint4*)(m16 + (size_t)s * HH + c);
    float2 f0 = __half22float2(*(__half2*)&raw.x);
    float2 f1 = __half22float2(*(__half2*)&raw.y);
    float2 f2 = __half22float2(*(__half2*)&raw.z);
    float2 f3 = __half22float2(*(__half2*)&raw.w);
    float* p = agg + (size_t)d * HH + c;
    asm volatile("red.global.add.v4.f32 [%0], {%1,%2,%3,%4};"
                 :: "l"(p), "f"(f0.x), "f"(f0.y), "f"(f1.x), "f"(f1.y) : "memory");
    asm volatile("red.global.add.v4.f32 [%0], {%1,%2,%3,%4};"
                 :: "l"(p + 4), "f"(f2.x), "f"(f2.y), "f"(f3.x), "f"(f3.y) : "memory");
}

// ---------------- head -------------------------------------------------------
__global__ void head_kernel(const float* __restrict__ h,
                            const float* __restrict__ W_lin,
                            const float* __restrict__ b_lin,
                            float* __restrict__ out)
{
    int gw = (blockIdx.x * blockDim.x + threadIdx.x) >> 5;
    int lane = threadIdx.x & 31;
    if (gw >= NN) return;
    const float* hr = h + (size_t)gw * HH;
    float a0 = 0.f, a1 = 0.f;
    #pragma unroll
    for (int k = lane; k < HH; k += 32) {
        float v = hr[k];
        v = v > 0.f ? v : 0.f;
        a0 += v * __ldg(W_lin + k);
        a1 += v * __ldg(W_lin + HH + k);
    }
    #pragma unroll
    for (int off = 16; off; off >>= 1) {
        a0 += __shfl_xor_sync(0xffffffffu, a0, off);
        a1 += __shfl_xor_sync(0xffffffffu, a1, off);
    }
    if (lane == 0) {
        float o0 = a0 + b_lin[0];
        float o1 = a1 + b_lin[1];
        float mx = fmaxf(o0, o1);
        float lse = mx + logf(expf(o0 - mx) + expf(o1 - mx));
        out[2*gw]     = o0 - lse;
        out[2*gw + 1] = o1 - lse;
    }
}

// ---------------- launch -----------------------------------------------------
extern "C" void kernel_launch(void* const* d_in, const int* in_sizes, int n_in,
                              void* d_out, int out_size)
{
    const float* x        = (const float*)d_in[0];
    const int*   edge     = (const int*)  d_in[1];
    const float* W_reduce = (const float*)d_in[3];
    const float* b_reduce = (const float*)d_in[4];
    const float* W_ggc    = (const float*)d_in[5];
    const float* W_ih     = (const float*)d_in[6];
    const float* W_hh     = (const float*)d_in[7];
    const float* b_ih     = (const float*)d_in[8];
    const float* b_hh     = (const float*)d_in[9];
    const float* W_lin    = (const float*)d_in[10];
    const float* b_lin    = (const float*)d_in[11];
    float* out = (float*)d_out;

    const int* src = edge;
    const int* dst = edge + NE;

    float *h0, *h1, *agg;
    __half *m16, *h16a, *h16b, *wred, *wggc, *wih, *whh;
    cudaGetSymbolAddress((void**)&h0,    g_h0);
    cudaGetSymbolAddress((void**)&h1,    g_h1);
    cudaGetSymbolAddress((void**)&agg,   g_agg);
    cudaGetSymbolAddress((void**)&m16,   g_m16);
    cudaGetSymbolAddress((void**)&h16a,  g_h16a);
    cudaGetSymbolAddress((void**)&h16b,  g_h16b);
    cudaGetSymbolAddress((void**)&wred,  g_wred);
    cudaGetSymbolAddress((void**)&wggc,  g_wggc);
    cudaGetSymbolAddress((void**)&wih,   g_wih);
    cudaGetSymbolAddress((void**)&whh,   g_whh);

    cudaFuncSetAttribute(mma_gemm,   cudaFuncAttributeMaxDynamicSharedMemorySize, SMEM_G);
    cudaFuncSetAttribute(mma_gemm16, cudaFuncAttributeMaxDynamicSharedMemorySize, SMEM_G);
    cudaFuncSetAttribute(gru_fused,  cudaFuncAttributeMaxDynamicSharedMemorySize, SMEM_F);

    const int mtiles128 = (NN + 127) / 128;   // 391

    // L1..L4 ordered so the profiled (4th) launch is mma_gemm16
    conv_w<<<(HH*KP + 255)/256, 256>>>(W_reduce, wred, HH, 200);                       // L1
    mma_gemm<<<dim3(HH/128, mtiles128), 256, SMEM_G>>>(x, wred, b_reduce,
                                                       h0, h16a, NN, HH, 200);        // L2
    conv_wggcT<<<(8*HH*KP + 255)/256, 256>>>(W_ggc, wggc);                             // L3

    float *hc32 = h0, *hn32 = h1;
    __half *hc16 = h16a, *hn16 = h16b;
    for (int s = 0; s < 8; s++) {
        mma_gemm16<<<dim3(HH/128, mtiles128), 256, SMEM_G>>>(hc16, wggc + (size_t)s*HH*KP,
                                                             m16, (float4*)agg, NN, HH); // L4 at s=0
        scatter_kernel<<<((long long)NE*32 + 255)/256, 256>>>(m16, src, dst, agg);
        if (s == 0) {
            conv_w<<<(H3*KP + 255)/256, 256>>>(W_ih, wih, H3, KP);
            conv_w<<<(H3*KP + 255)/256, 256>>>(W_hh, whh, H3, KP);
        }
        gru_fused<<<dim3(HH/64, mtiles128), 256, SMEM_F>>>(agg, hc16, hc32, wih, whh,
                                                           b_ih, b_hh, hn32, hn16, NN);
        { float* t = hc32; hc32 = hn32; hn32 = t; }
        { __half* t = hc16; hc16 = hn16; hn16 = t; }
    }

    head_kernel<<<(NN*32 + 255)/256, 256>>>(hc32, W_lin, b_lin, out);
}

// round 12
// speedup vs baseline: 1.0512x; 1.0512x over previous
#include <cuda_runtime.h>
#include <cuda_fp16.h>
#include <math.h>
#include <stdint.h>

#define NN 50000
#define HH 256
#define NE 300000
#define H3 (3*HH)
#define KP 256
#define NPAD (NN + 128)

// ---------------- scratch ----------------------------------------------------
__device__ float g_h0[NN*HH];
__device__ float g_h1[NN*HH];
__device__ float g_agg[NN*HH];
__device__ __half g_m16[(size_t)NN*HH];
__device__ __half g_h16a[(size_t)NPAD*HH];
__device__ __half g_h16b[(size_t)NPAD*HH];

// fp16 weights, [rows, 256] K-major
__device__ __half g_wred[HH*KP];
__device__ __half g_wggc[8*HH*KP];
__device__ __half g_wih[H3*KP];
__device__ __half g_whh[H3*KP];

// ---------------- weight conversion ------------------------------------------
__global__ void conv_w(const float* __restrict__ W, __half* __restrict__ o,
                       int Nrows, int Ksrc)
{
    int t = blockIdx.x * blockDim.x + threadIdx.x;
    if (t >= Nrows * KP) return;
    int n = t >> 8, k = t & 255;
    float v = (k < Ksrc) ? W[(size_t)n * Ksrc + k] : 0.f;
    o[t] = __float2half_rn(v);
}

__global__ void conv_wggcT(const float* __restrict__ W, __half* __restrict__ o)
{
    int t = blockIdx.x * blockDim.x + threadIdx.x;
    if (t >= 8 * HH * KP) return;
    int s = t >> 16, n = (t >> 8) & 255, k = t & 255;
    o[t] = __float2half_rn(W[((size_t)s << 16) + (size_t)k * HH + n]);
}

// ---------------- asm helpers ------------------------------------------------
__device__ __forceinline__ uint32_t smem_u32(const void* p) {
    uint32_t a;
    asm("{ .reg .u64 t; cvta.to.shared.u64 t, %1; cvt.u32.u64 %0, t; }" : "=r"(a) : "l"(p));
    return a;
}
__device__ __forceinline__ void ldmx4(uint32_t* r, uint32_t addr) {
    asm volatile("ldmatrix.sync.aligned.m8n8.x4.shared.b16 {%0,%1,%2,%3}, [%4];"
                 : "=r"(r[0]), "=r"(r[1]), "=r"(r[2]), "=r"(r[3]) : "r"(addr));
}
__device__ __forceinline__ void mma16816(float* d, const uint32_t* a, uint32_t b0, uint32_t b1) {
    asm volatile(
        "mma.sync.aligned.m16n8k16.row.col.f32.f16.f16.f32 "
        "{%0,%1,%2,%3}, {%4,%5,%6,%7}, {%8,%9}, {%0,%1,%2,%3};"
        : "+f"(d[0]), "+f"(d[1]), "+f"(d[2]), "+f"(d[3])
        : "r"(a[0]), "r"(a[1]), "r"(a[2]), "r"(a[3]), "r"(b0), "r"(b1));
}
__device__ __forceinline__ void cpa16(uint32_t dst, const void* src) {
    asm volatile("cp.async.ca.shared.global [%0], [%1], 16;" :: "r"(dst), "l"(src) : "memory");
}
__device__ __forceinline__ void cpa_commit() {
    asm volatile("cp.async.commit_group;" ::: "memory");
}
__device__ __forceinline__ void cpa_wait0() {
    asm volatile("cp.async.wait_group 0;" ::: "memory");
}
__device__ __forceinline__ void cpa_wait1() {
    asm volatile("cp.async.wait_group 1;" ::: "memory");
}

#define LDSW 40

// ============ GEMM A=fp32 (reduce): C = A @ B^T + bias, writes f32 + f16 ====
#define ARR (128*LDSW)
#define STG (2*ARR)
#define SMEM_G (2*STG*2)

__global__ __launch_bounds__(256)
void mma_gemm(const float* __restrict__ A, const __half* __restrict__ B,
              const float* __restrict__ bias, float* __restrict__ C,
              __half* __restrict__ C16, int M, int N, int Ksrc)
{
    extern __shared__ __half smp[];
    const int tid = threadIdx.x, lane = tid & 31, wid = tid >> 5;
    const int bm = blockIdx.y * 128, bn = blockIdx.x * 128;
    const int wm = (wid & 3) * 32, wn = (wid >> 2) * 64;

    float c[2][8][4];
    #pragma unroll
    for (int i = 0; i < 2; i++)
        #pragma unroll
        for (int j = 0; j < 8; j++)
            #pragma unroll
            for (int q = 0; q < 4; q++) c[i][j][q] = 0.f;

    const int lrow = tid >> 1, lcol = (tid & 1) * 16;
    const bool rv = (bm + lrow) < M;
    const float* Arow = A + (size_t)(bm + lrow) * Ksrc + lcol;
    const __half* Brow = B + (size_t)(bn + lrow) * KP + lcol;

    const uint32_t u0 = smem_u32(smp);
    const int lodst = lrow * LDSW + lcol;
    const uint32_t bdst = u0 + (uint32_t)(ARR + lodst) * 2;

    const int aro = (lane & 7) + ((lane >> 3) & 1) * 8;
    const int ako = ((lane >> 4) & 1) * 8;
    const int bro = (lane & 7) + ((lane >> 4) & 1) * 8;
    const int bko = ((lane >> 3) & 1) * 8;

    {
        #pragma unroll
        for (int q = 0; q < 4; q++) {
            int k = lcol + q * 4;
            float4 v = make_float4(0.f,0.f,0.f,0.f);
            if (rv && k < Ksrc) v = *(const float4*)(Arow + q * 4);
            __half2 p0 = __floats2half2_rn(v.x, v.y);
            __half2 p1 = __floats2half2_rn(v.z, v.w);
            int o = lodst + q * 4;
            *(__half2*)&smp[o] = p0; *(__half2*)&smp[o+2] = p1;
        }
        cpa16(bdst, Brow); cpa16(bdst + 16, Brow + 8);
        cpa_commit();
    }

    for (int ch = 0; ch < 8; ch++) {
        const int cur = ch & 1, nxt = cur ^ 1;
        cpa_wait0();
        __syncthreads();
        float ar[16];
        if (ch < 7) {
            const int kn = (ch + 1) * 32;
            #pragma unroll
            for (int q = 0; q < 4; q++) {
                int k = kn + lcol + q * 4;
                float4 v = make_float4(0.f,0.f,0.f,0.f);
                if (rv && k < Ksrc) v = *(const float4*)(Arow + kn + q * 4);
                ar[q*4+0]=v.x; ar[q*4+1]=v.y; ar[q*4+2]=v.z; ar[q*4+3]=v.w;
            }
            const uint32_t sb = (uint32_t)(nxt * STG) * 2;
            cpa16(bdst + sb, Brow + kn); cpa16(bdst + sb + 16, Brow + kn + 8);
            cpa_commit();
        }
        const uint32_t base = u0 + (uint32_t)(cur * STG) * 2;
        const uint32_t uA = base, uB = base + ARR * 2;
        #pragma unroll
        for (int kh = 0; kh < 2; kh++) {
            const int kb = kh * 16;
            uint32_t ah[2][4];
            #pragma unroll
            for (int mt = 0; mt < 2; mt++)
                ldmx4(ah[mt], uA + (uint32_t)(((wm + mt*16 + aro) * LDSW + kb + ako) * 2));
            #pragma unroll
            for (int ng = 0; ng < 4; ng++) {
                uint32_t bh[4];
                ldmx4(bh, uB + (uint32_t)(((wn + ng*16 + bro) * LDSW + kb + bko) * 2));
                #pragma unroll
                for (int mt = 0; mt < 2; mt++) {
                    mma16816(c[mt][2*ng],   ah[mt], bh[0], bh[1]);
                    mma16816(c[mt][2*ng+1], ah[mt], bh[2], bh[3]);
                }
            }
        }
        if (ch < 7) {
            __half* sA = smp + nxt * STG;
            #pragma unroll
            for (int q = 0; q < 4; q++) {
                __half2 p0 = __floats2half2_rn(ar[q*4+0], ar[q*4+1]);
                __half2 p1 = __floats2half2_rn(ar[q*4+2], ar[q*4+3]);
                int o = lodst + q * 4;
                *(__half2*)&sA[o] = p0; *(__half2*)&sA[o+2] = p1;
            }
        }
    }

    #pragma unroll
    for (int mt = 0; mt < 2; mt++) {
        int row = bm + wm + mt * 16 + (lane >> 2);
        #pragma unroll
        for (int nidx = 0; nidx < 8; nidx++) {
            int col = bn + wn + nidx * 8 + (lane & 3) * 2;
            float b0 = 0.f, b1 = 0.f;
            if (bias) { b0 = bias[col]; b1 = bias[col + 1]; }
            float v00 = c[mt][nidx][0] + b0, v01 = c[mt][nidx][1] + b1;
            float v10 = c[mt][nidx][2] + b0, v11 = c[mt][nidx][3] + b1;
            if (row < M) {
                *(float2*)(C + (size_t)row * N + col) = make_float2(v00, v01);
                *(__half2*)(C16 + (size_t)row * N + col) = __floats2half2_rn(v00, v01);
            }
            if (row + 8 < M) {
                *(float2*)(C + (size_t)(row + 8) * N + col) = make_float2(v10, v11);
                *(__half2*)(C16 + (size_t)(row + 8) * N + col) = __floats2half2_rn(v10, v11);
            }
        }
    }
}

// ============ GEMM A=fp16 (ggc): 3-stage pipeline, fp16 out, zeroes agg =====
#define NSTG3 3
#define SMEM_G16 (NSTG3*STG*2)

__global__ __launch_bounds__(256)
void mma_gemm16(const __half* __restrict__ A, const __half* __restrict__ B,
                __half* __restrict__ C16, float4* __restrict__ aggz,
                int M, int N)
{
    extern __shared__ __half smp[];
    const int tid = threadIdx.x, lane = tid & 31, wid = tid >> 5;
    const int bm = blockIdx.y * 128, bn = blockIdx.x * 128;
    const int wm = (wid & 3) * 32, wn = (wid >> 2) * 64;

    float c[2][8][4];
    #pragma unroll
    for (int i = 0; i < 2; i++)
        #pragma unroll
        for (int j = 0; j < 8; j++)
            #pragma unroll
            for (int q = 0; q < 4; q++) c[i][j][q] = 0.f;

    const int lrow = tid >> 1, lcol = (tid & 1) * 16;
    const __half* Arow = A + (size_t)(bm + lrow) * KP + lcol;
    const __half* Brow = B + (size_t)(bn + lrow) * KP + lcol;

    const uint32_t u0 = smem_u32(smp);
    const int lodst = lrow * LDSW + lcol;
    const uint32_t adst = u0 + (uint32_t)lodst * 2;
    const uint32_t bdst = u0 + (uint32_t)(ARR + lodst) * 2;

    const int aro = (lane & 7) + ((lane >> 3) & 1) * 8;
    const int ako = ((lane >> 4) & 1) * 8;
    const int bro = (lane & 7) + ((lane >> 4) & 1) * 8;
    const int bko = ((lane >> 3) & 1) * 8;

    // prologue: stages 0 and 1 (chunks 0, 1)
    cpa16(adst, Arow); cpa16(adst + 16, Arow + 8);
    cpa16(bdst, Brow); cpa16(bdst + 16, Brow + 8);
    cpa_commit();
    {
        const uint32_t sb = (uint32_t)STG * 2;
        cpa16(adst + sb, Arow + 32); cpa16(adst + sb + 16, Arow + 40);
        cpa16(bdst + sb, Brow + 32); cpa16(bdst + sb + 16, Brow + 40);
        cpa_commit();
    }

    // ---- zero a slice of agg (runs right before scatter in-stream) ----
    {
        const int nblk = gridDim.x * gridDim.y;
        const int slice = blockIdx.y * gridDim.x + blockIdx.x;
        const int total4 = NN * HH / 4;
        const int per = (total4 + nblk - 1) / nblk;
        int s0 = slice * per;
        int s1 = min(s0 + per, total4);
        const float4 z = make_float4(0.f,0.f,0.f,0.f);
        for (int i = s0 + tid; i < s1; i += 256) aggz[i] = z;
    }

    int cur = 0;
    for (int ch = 0; ch < 8; ch++) {
        if (ch < 7) cpa_wait1(); else cpa_wait0();
        __syncthreads();
        if (ch + 2 < 8) {
            const int kn = (ch + 2) * 32;
            int pst = cur + 2; if (pst >= NSTG3) pst -= NSTG3;
            const uint32_t sb = (uint32_t)(pst * STG) * 2;
            cpa16(adst + sb, Arow + kn); cpa16(adst + sb + 16, Arow + kn + 8);
            cpa16(bdst + sb, Brow + kn); cpa16(bdst + sb + 16, Brow + kn + 8);
            cpa_commit();
        }
        const uint32_t base = u0 + (uint32_t)(cur * STG) * 2;
        const uint32_t uA = base, uB = base + ARR * 2;
        #pragma unroll
        for (int kh = 0; kh < 2; kh++) {
            const int kb = kh * 16;
            uint32_t ah[2][4];
            #pragma unroll
            for (int mt = 0; mt < 2; mt++)
                ldmx4(ah[mt], uA + (uint32_t)(((wm + mt*16 + aro) * LDSW + kb + ako) * 2));
            #pragma unroll
            for (int ng = 0; ng < 4; ng++) {
                uint32_t bh[4];
                ldmx4(bh, uB + (uint32_t)(((wn + ng*16 + bro) * LDSW + kb + bko) * 2));
                #pragma unroll
                for (int mt = 0; mt < 2; mt++) {
                    mma16816(c[mt][2*ng],   ah[mt], bh[0], bh[1]);
                    mma16816(c[mt][2*ng+1], ah[mt], bh[2], bh[3]);
                }
            }
        }
        cur++; if (cur >= NSTG3) cur -= NSTG3;
    }

    #pragma unroll
    for (int mt = 0; mt < 2; mt++) {
        int row = bm + wm + mt * 16 + (lane >> 2);
        #pragma unroll
        for (int nidx = 0; nidx < 8; nidx++) {
            int col = bn + wn + nidx * 8 + (lane & 3) * 2;
            if (row < M)
                *(__half2*)(C16 + (size_t)row * N + col) =
                    __floats2half2_rn(c[mt][nidx][0], c[mt][nidx][1]);
            if (row + 8 < M)
                *(__half2*)(C16 + (size_t)(row + 8) * N + col) =
                    __floats2half2_rn(c[mt][nidx][2], c[mt][nidx][3]);
        }
    }
}

// ============ fused gi+gh GEMM + GRU (R10 config: K32, 100KB smem) ==========
#define ARRA (128*LDSW)
#define ARRW (64*LDSW)
#define STGF (2*ARRA + 6*ARRW)
#define SMEM_F (2*STGF*2)

__global__ __launch_bounds__(256)
void gru_fused(const float* __restrict__ agg32, const __half* __restrict__ h16,
               const float* __restrict__ h32,
               const __half* __restrict__ Wih, const __half* __restrict__ Whh,
               const float* __restrict__ b_ih, const float* __restrict__ b_hh,
               float* __restrict__ h32n, __half* __restrict__ h16n, int M)
{
    extern __shared__ __half smp[];
    const int tid = threadIdx.x, lane = tid & 31, wid = tid >> 5;
    const int bm = blockIdx.y * 128, bn = blockIdx.x * 64;
    const int wm = (wid & 3) * 32, wn = (wid >> 2) * 32;

    float cr[2][4][4], cz[2][4][4], cin[2][4][4], chn[2][4][4];
    #pragma unroll
    for (int mt = 0; mt < 2; mt++)
        #pragma unroll
        for (int f = 0; f < 4; f++)
            #pragma unroll
            for (int q = 0; q < 4; q++)
            { cr[mt][f][q]=0.f; cz[mt][f][q]=0.f; cin[mt][f][q]=0.f; chn[mt][f][q]=0.f; }

    const int arow = tid >> 1, aseg = (tid & 1) * 16;
    const bool rv = (bm + arow) < M;
    const float* pAg = agg32 + (size_t)(bm + arow) * HH + aseg;
    const __half* pAh = h16   + (size_t)(bm + arow) * KP + aseg;
    const int wrow = tid >> 2, wseg = (tid & 3) * 8;
    const __half* pW[6];
    pW[0] = Wih + (size_t)(bn + wrow) * KP + wseg;
    pW[1] = Whh + (size_t)(bn + wrow) * KP + wseg;
    pW[2] = Wih + (size_t)(256 + bn + wrow) * KP + wseg;
    pW[3] = Whh + (size_t)(256 + bn + wrow) * KP + wseg;
    pW[4] = Wih + (size_t)(512 + bn + wrow) * KP + wseg;
    pW[5] = Whh + (size_t)(512 + bn + wrow) * KP + wseg;

    const uint32_t u0 = smem_u32(smp);
    const int aodst = arow * LDSW + aseg;
    const uint32_t ahdst = u0 + (uint32_t)(ARRA + aodst) * 2;
    const uint32_t wdst0 = u0 + (uint32_t)(2*ARRA + wrow * LDSW + wseg) * 2;

    const int aro = (lane & 7) + ((lane >> 3) & 1) * 8;
    const int ako = ((lane >> 4) & 1) * 8;
    const int bro = (lane & 7) + ((lane >> 4) & 1) * 8;
    const int bko = ((lane >> 3) & 1) * 8;

    {
        #pragma unroll
        for (int q = 0; q < 4; q++) {
            float4 v = rv ? *(const float4*)(pAg + q * 4) : make_float4(0.f,0.f,0.f,0.f);
            __half2 p0 = __floats2half2_rn(v.x, v.y);
            __half2 p1 = __floats2half2_rn(v.z, v.w);
            int o = aodst + q * 4;
            *(__half2*)&smp[o] = p0; *(__half2*)&smp[o+2] = p1;
        }
        cpa16(ahdst, pAh); cpa16(ahdst + 16, pAh + 8);
        #pragma unroll
        for (int s = 0; s < 6; s++)
            cpa16(wdst0 + (uint32_t)(s * ARRW) * 2, pW[s]);
        cpa_commit();
    }

    for (int ch = 0; ch < 8; ch++) {
        const int cur = ch & 1, nxt = cur ^ 1;
        cpa_wait0();
        __syncthreads();
        float ar[16];
        if (ch < 7) {
            const int kn = (ch + 1) * 32;
            #pragma unroll
            for (int q = 0; q < 4; q++) {
                float4 v = rv ? *(const float4*)(pAg + kn + q * 4) : make_float4(0.f,0.f,0.f,0.f);
                ar[q*4+0]=v.x; ar[q*4+1]=v.y; ar[q*4+2]=v.z; ar[q*4+3]=v.w;
            }
            const uint32_t sb = (uint32_t)(nxt * STGF) * 2;
            cpa16(ahdst + sb, pAh + kn); cpa16(ahdst + sb + 16, pAh + kn + 8);
            #pragma unroll
            for (int s = 0; s < 6; s++)
                cpa16(wdst0 + sb + (uint32_t)(s * ARRW) * 2, pW[s] + kn);
            cpa_commit();
        }

        const uint32_t base = u0 + (uint32_t)(cur * STGF) * 2;
        const uint32_t uAg = base, uAh = base + (uint32_t)ARRA * 2;
        #pragma unroll
        for (int kh = 0; kh < 2; kh++) {
            const int kb = kh * 16;
            uint32_t ag[2][4], ah[2][4];
            #pragma unroll
            for (int mt = 0; mt < 2; mt++) {
                const uint32_t ao = (uint32_t)(((wm + mt*16 + aro) * LDSW + kb + ako) * 2);
                ldmx4(ag[mt], uAg + ao);
                ldmx4(ah[mt], uAh + ao);
            }
            #pragma unroll
            for (int ng = 0; ng < 2; ng++) {
                const uint32_t bo = (uint32_t)(((wn + ng*16 + bro) * LDSW + kb + bko) * 2);
                uint32_t bb[4];
                ldmx4(bb, base + (uint32_t)(2*ARRA + 0*ARRW) * 2 + bo);
                #pragma unroll
                for (int mt = 0; mt < 2; mt++) {
                    mma16816(cr[mt][2*ng],   ag[mt], bb[0], bb[1]);
                    mma16816(cr[mt][2*ng+1], ag[mt], bb[2], bb[3]);
                }
                ldmx4(bb, base + (uint32_t)(2*ARRA + 1*ARRW) * 2 + bo);
                #pragma unroll
                for (int mt = 0; mt < 2; mt++) {
                    mma16816(cr[mt][2*ng],   ah[mt], bb[0], bb[1]);
                    mma16816(cr[mt][2*ng+1], ah[mt], bb[2], bb[3]);
                }
                ldmx4(bb, base + (uint32_t)(2*ARRA + 2*ARRW) * 2 + bo);
                #pragma unroll
                for (int mt = 0; mt < 2; mt++) {
                    mma16816(cz[mt][2*ng],   ag[mt], bb[0], bb[1]);
                    mma16816(cz[mt][2*ng+1], ag[mt], bb[2], bb[3]);
                }
                ldmx4(bb, base + (uint32_t)(2*ARRA + 3*ARRW) * 2 + bo);
                #pragma unroll
                for (int mt = 0; mt < 2; mt++) {
                    mma16816(cz[mt][2*ng],   ah[mt], bb[0], bb[1]);
                    mma16816(cz[mt][2*ng+1], ah[mt], bb[2], bb[3]);
                }
                ldmx4(bb, base + (uint32_t)(2*ARRA + 4*ARRW) * 2 + bo);
                #pragma unroll
                for (int mt = 0; mt < 2; mt++) {
                    mma16816(cin[mt][2*ng],   ag[mt], bb[0], bb[1]);
                    mma16816(cin[mt][2*ng+1], ag[mt], bb[2], bb[3]);
                }
                ldmx4(bb, base + (uint32_t)(2*ARRA + 5*ARRW) * 2 + bo);
                #pragma unroll
                for (int mt = 0; mt < 2; mt++) {
                    mma16816(chn[mt][2*ng],   ah[mt], bb[0], bb[1]);
                    mma16816(chn[mt][2*ng+1], ah[mt], bb[2], bb[3]);
                }
            }
        }

        if (ch < 7) {
            __half* sA = smp + nxt * STGF;
            #pragma unroll
            for (int q = 0; q < 4; q++) {
                __half2 p0 = __floats2half2_rn(ar[q*4+0], ar[q*4+1]);
                __half2 p1 = __floats2half2_rn(ar[q*4+2], ar[q*4+3]);
                int o = aodst + q * 4;
                *(__half2*)&sA[o] = p0; *(__half2*)&sA[o+2] = p1;
            }
        }
    }

    #pragma unroll
    for (int mt = 0; mt < 2; mt++) {
        const int r0 = bm + wm + mt * 16 + (lane >> 2);
        #pragma unroll
        for (int f = 0; f < 4; f++) {
            const int col = bn + wn + f * 8 + (lane & 3) * 2;
            const float br0 = __ldg(b_ih + col)       + __ldg(b_hh + col);
            const float br1 = __ldg(b_ih + col + 1)   + __ldg(b_hh + col + 1);
            const float bz0 = __ldg(b_ih + 256 + col) + __ldg(b_hh + 256 + col);
            const float bz1 = __ldg(b_ih + 257 + col) + __ldg(b_hh + 257 + col);
            const float bin0 = __ldg(b_ih + 512 + col),   bin1 = __ldg(b_ih + 513 + col);
            const float bhn0 = __ldg(b_hh + 512 + col),   bhn1 = __ldg(b_hh + 513 + col);
            #pragma unroll
            for (int e = 0; e < 2; e++) {
                const int row = r0 + e * 8;
                if (row >= M) continue;
                float2 hv = *(const float2*)(h32 + (size_t)row * HH + col);
                float rr0 = 1.f / (1.f + __expf(-(cr[mt][f][2*e]   + br0)));
                float rr1 = 1.f / (1.f + __expf(-(cr[mt][f][2*e+1] + br1)));
                float zz0 = 1.f / (1.f + __expf(-(cz[mt][f][2*e]   + bz0)));
                float zz1 = 1.f / (1.f + __expf(-(cz[mt][f][2*e+1] + bz1)));
                float nn0 = tanhf(cin[mt][f][2*e]   + bin0 + rr0 * (chn[mt][f][2*e]   + bhn0));
                float nn1 = tanhf(cin[mt][f][2*e+1] + bin1 + rr1 * (chn[mt][f][2*e+1] + bhn1));
                float o0 = (1.f - zz0) * nn0 + zz0 * hv.x;
                float o1 = (1.f - zz1) * nn1 + zz1 * hv.y;
                *(float2*)(h32n + (size_t)row * HH + col) = make_float2(o0, o1);
                *(__half2*)(h16n + (size_t)row * HH + col) = __floats2half2_rn(o0, o1);
            }
        }
    }
}

// ---------------- scatter: agg[dst] += m16[src] (32 threads/edge) -----------
__global__ void scatter_kernel(const __half* __restrict__ m16,
                               const int* __restrict__ src,
                               const int* __restrict__ dst,
                               float* __restrict__ agg)
{
    long long t = (long long)blockIdx.x * blockDim.x + threadIdx.x;
    int e = (int)(t >> 5);
    if (e >= NE) return;
    int c = ((int)t & 31) << 3;
    int s = __ldg(src + e);
    int d = __ldg(dst + e);
    uint4 raw = *(const uint4*)(m16 + (size_t)s * HH + c);
    float2 f0 = __half22float2(*(__half2*)&raw.x);
    float2 f1 = __half22float2(*(__half2*)&raw.y);
    float2 f2 = __half22float2(*(__half2*)&raw.z);
    float2 f3 = __half22float2(*(__half2*)&raw.w);
    float* p = agg + (size_t)d * HH + c;
    asm volatile("red.global.add.v4.f32 [%0], {%1,%2,%3,%4};"
                 :: "l"(p), "f"(f0.x), "f"(f0.y), "f"(f1.x), "f"(f1.y) : "memory");
    asm volatile("red.global.add.v4.f32 [%0], {%1,%2,%3,%4};"
                 :: "l"(p + 4), "f"(f2.x), "f"(f2.y), "f"(f3.x), "f"(f3.y) : "memory");
}

// ---------------- head -------------------------------------------------------
__global__ void head_kernel(const float* __restrict__ h,
                            const float* __restrict__ W_lin,
                            const float* __restrict__ b_lin,
                            float* __restrict__ out)
{
    int gw = (blockIdx.x * blockDim.x + threadIdx.x) >> 5;
    int lane = threadIdx.x & 31;
    if (gw >= NN) return;
    const float* hr = h + (size_t)gw * HH;
    float a0 = 0.f, a1 = 0.f;
    #pragma unroll
    for (int k = lane; k < HH; k += 32) {
        float v = hr[k];
        v = v > 0.f ? v : 0.f;
        a0 += v * __ldg(W_lin + k);
        a1 += v * __ldg(W_lin + HH + k);
    }
    #pragma unroll
    for (int off = 16; off; off >>= 1) {
        a0 += __shfl_xor_sync(0xffffffffu, a0, off);
        a1 += __shfl_xor_sync(0xffffffffu, a1, off);
    }
    if (lane == 0) {
        float o0 = a0 + b_lin[0];
        float o1 = a1 + b_lin[1];
        float mx = fmaxf(o0, o1);
        float lse = mx + logf(expf(o0 - mx) + expf(o1 - mx));
        out[2*gw]     = o0 - lse;
        out[2*gw + 1] = o1 - lse;
    }
}

// ---------------- launch -----------------------------------------------------
extern "C" void kernel_launch(void* const* d_in, const int* in_sizes, int n_in,
                              void* d_out, int out_size)
{
    const float* x        = (const float*)d_in[0];
    const int*   edge     = (const int*)  d_in[1];
    const float* W_reduce = (const float*)d_in[3];
    const float* b_reduce = (const float*)d_in[4];
    const float* W_ggc    = (const float*)d_in[5];
    const float* W_ih     = (const float*)d_in[6];
    const float* W_hh     = (const float*)d_in[7];
    const float* b_ih     = (const float*)d_in[8];
    const float* b_hh     = (const float*)d_in[9];
    const float* W_lin    = (const float*)d_in[10];
    const float* b_lin    = (const float*)d_in[11];
    float* out = (float*)d_out;

    const int* src = edge;
    const int* dst = edge + NE;

    float *h0, *h1, *agg;
    __half *m16, *h16a, *h16b, *wred, *wggc, *wih, *whh;
    cudaGetSymbolAddress((void**)&h0,    g_h0);
    cudaGetSymbolAddress((void**)&h1,    g_h1);
    cudaGetSymbolAddress((void**)&agg,   g_agg);
    cudaGetSymbolAddress((void**)&m16,   g_m16);
    cudaGetSymbolAddress((void**)&h16a,  g_h16a);
    cudaGetSymbolAddress((void**)&h16b,  g_h16b);
    cudaGetSymbolAddress((void**)&wred,  g_wred);
    cudaGetSymbolAddress((void**)&wggc,  g_wggc);
    cudaGetSymbolAddress((void**)&wih,   g_wih);
    cudaGetSymbolAddress((void**)&whh,   g_whh);

    cudaFuncSetAttribute(mma_gemm,   cudaFuncAttributeMaxDynamicSharedMemorySize, SMEM_G);
    cudaFuncSetAttribute(mma_gemm16, cudaFuncAttributeMaxDynamicSharedMemorySize, SMEM_G16);
    cudaFuncSetAttribute(gru_fused,  cudaFuncAttributeMaxDynamicSharedMemorySize, SMEM_F);

    const int mtiles128 = (NN + 127) / 128;   // 391

    // ordered so the profiled (4th) launch is mma_gemm16
    conv_w<<<(HH*KP + 255)/256, 256>>>(W_reduce, wred, HH, 200);                       // L1
    mma_gemm<<<dim3(HH/128, mtiles128), 256, SMEM_G>>>(x, wred, b_reduce,
                                                       h0, h16a, NN, HH, 200);        // L2
    conv_wggcT<<<(8*HH*KP + 255)/256, 256>>>(W_ggc, wggc);                             // L3

    float *hc32 = h0, *hn32 = h1;
    __half *hc16 = h16a, *hn16 = h16b;
    for (int s = 0; s < 8; s++) {
        mma_gemm16<<<dim3(HH/128, mtiles128), 256, SMEM_G16>>>(hc16, wggc + (size_t)s*HH*KP,
                                                               m16, (float4*)agg, NN, HH); // L4 at s=0
        scatter_kernel<<<((long long)NE*32 + 255)/256, 256>>>(m16, src, dst, agg);
        if (s == 0) {
            conv_w<<<(H3*KP + 255)/256, 256>>>(W_ih, wih, H3, KP);
            conv_w<<<(H3*KP + 255)/256, 256>>>(W_hh, whh, H3, KP);
        }
        gru_fused<<<dim3(HH/64, mtiles128), 256, SMEM_F>>>(agg, hc16, hc32, wih, whh,
                                                           b_ih, b_hh, hn32, hn16, NN);
        { float* t = hc32; hc32 = hn32; hn32 = t; }
        { __half* t = hc16; hc16 = hn16; hn16 = t; }
    }

    head_kernel<<<(NN*32 + 255)/256, 256>>>(hc32, W_lin, b_lin, out);
}